// round 2
// baseline (speedup 1.0000x reference)
#include <cuda_runtime.h>

#define N_NODE   100000
#define D_IN     256
#define D_OUT    64
#define E_MAX    1600000
#define NEG_SLOPE 0.2f

// ---- scratch (static __device__ globals; no allocation in kernel_launch) ----
__device__ float g_xl[N_NODE * D_IN];   // emb @ W_l   [N, 256]
__device__ float g_xr[N_NODE * D_IN];   // emb @ W_r   [N, 256]
__device__ int   g_cnt[N_NODE];         // in-degree (real edges only)
__device__ int   g_incl[N_NODE];        // inclusive prefix sum of cnt
__device__ int   g_cursor[N_NODE];      // scatter cursors
__device__ int   g_srcs[E_MAX];         // CSR src indices grouped by dst
__device__ int   g_bsum[256];           // scan block sums

// ============================================================
// SGEMM: C[M,256] = A[M,256] @ B[256,256], fp32, 128x128x8 tiles
// WHICH: 0 -> g_xl, 1 -> g_xr
// ============================================================
template <int WHICH>
__global__ void __launch_bounds__(256)
sgemm128(const float* __restrict__ A, const float* __restrict__ B, int M)
{
    __shared__ float As[8][128];
    __shared__ float Bs[8][128];

    float* C = WHICH ? g_xr : g_xl;

    const int tid = threadIdx.x;
    const int bx = blockIdx.x;      // 0..1 (N=256 / 128)
    const int by = blockIdx.y;
    const int ty = tid >> 4;        // 0..15
    const int tx = tid & 15;        // 0..15

    float acc[8][8];
#pragma unroll
    for (int i = 0; i < 8; i++)
#pragma unroll
        for (int j = 0; j < 8; j++) acc[i][j] = 0.f;

    // A tile load mapping: 128 rows x 8 k, float4 along k
    const int arow = tid >> 1;            // 0..127
    const int ak4  = (tid & 1) * 4;       // 0 or 4
    const int grow = by * 128 + arow;
    const bool aval = (grow < M);
    const float* Aptr = A + (long long)grow * D_IN + ak4;

    // B tile load mapping: 8 k rows x 128 cols, float4 along n
    const int brow = tid >> 5;            // 0..7
    const int bcol = (tid & 31) * 4;      // 0..124
    const float* Bptr = B + brow * 256 + bx * 128 + bcol;

    for (int kt = 0; kt < 256; kt += 8) {
        float4 av = aval ? *(const float4*)(Aptr + kt)
                         : make_float4(0.f, 0.f, 0.f, 0.f);
        As[ak4 + 0][arow] = av.x;
        As[ak4 + 1][arow] = av.y;
        As[ak4 + 2][arow] = av.z;
        As[ak4 + 3][arow] = av.w;
        *(float4*)&Bs[brow][bcol] = *(const float4*)(Bptr + kt * 256);
        __syncthreads();

#pragma unroll
        for (int k = 0; k < 8; k++) {
            float a[8], b[8];
            *(float4*)&a[0] = *(const float4*)&As[k][ty * 8];
            *(float4*)&a[4] = *(const float4*)&As[k][ty * 8 + 4];
            *(float4*)&b[0] = *(const float4*)&Bs[k][tx * 8];
            *(float4*)&b[4] = *(const float4*)&Bs[k][tx * 8 + 4];
#pragma unroll
            for (int i = 0; i < 8; i++)
#pragma unroll
                for (int j = 0; j < 8; j++)
                    acc[i][j] += a[i] * b[j];
        }
        __syncthreads();
    }

    const int col0 = bx * 128 + tx * 8;
#pragma unroll
    for (int i = 0; i < 8; i++) {
        int row = by * 128 + ty * 8 + i;
        if (row < M) {
            *(float4*)&C[(long long)row * D_IN + col0]     = *(float4*)&acc[i][0];
            *(float4*)&C[(long long)row * D_IN + col0 + 4] = *(float4*)&acc[i][4];
        }
    }
}

// ============================================================
// CSR construction  (edge_index is int32: row 0 = src, row 1 = dst)
// ============================================================
__global__ void zero_cnt_k(int M)
{
    int i = blockIdx.x * blockDim.x + threadIdx.x;
    if (i < M) g_cnt[i] = 0;
}

__global__ void count_k(const int* __restrict__ ei, int E)
{
    int e = blockIdx.x * blockDim.x + threadIdx.x;
    if (e < E) {
        int d = ei[E + e];
        atomicAdd(&g_cnt[d], 1);
    }
}

__global__ void scan1_k(int M)
{
    __shared__ int s[1024];
    int gi = blockIdx.x * 1024 + threadIdx.x;
    int v = (gi < M) ? g_cnt[gi] : 0;
    s[threadIdx.x] = v;
    __syncthreads();
#pragma unroll
    for (int off = 1; off < 1024; off <<= 1) {
        int t = (threadIdx.x >= off) ? s[threadIdx.x - off] : 0;
        __syncthreads();
        s[threadIdx.x] += t;
        __syncthreads();
    }
    if (gi < M) g_incl[gi] = s[threadIdx.x];
    if (threadIdx.x == 1023) g_bsum[blockIdx.x] = s[1023];
}

__global__ void scan2_k(int nb)
{
    if (threadIdx.x == 0 && blockIdx.x == 0) {
        int run = 0;
        for (int b = 0; b < nb; b++) {
            int t = g_bsum[b];
            g_bsum[b] = run;
            run += t;
        }
    }
}

__global__ void scan3_k(int M)
{
    int i = blockIdx.x * blockDim.x + threadIdx.x;
    if (i < M) {
        int incl = g_incl[i] + g_bsum[i >> 10];
        g_incl[i] = incl;
        g_cursor[i] = incl - g_cnt[i];   // row start
    }
}

__global__ void scatter_k(const int* __restrict__ ei, int E)
{
    int e = blockIdx.x * blockDim.x + threadIdx.x;
    if (e < E) {
        int d = ei[E + e];
        int pos = atomicAdd(&g_cursor[d], 1);
        g_srcs[pos] = ei[e];
    }
}

// ============================================================
// Per-node GATv2 attention + aggregation, one warp per dst node.
// Online softmax: single pass over incoming edges.
// Lane owns channels c = lane + 32*k, k=0..7; head(c) = k>>1.
// ============================================================
__global__ void __launch_bounds__(256)
agg_k(const float* __restrict__ att, const float* __restrict__ bias,
      float* __restrict__ out, int M)
{
    const int gwarp = (blockIdx.x * blockDim.x + threadIdx.x) >> 5;
    const int lane = threadIdx.x & 31;
    if (gwarp >= M) return;
    const int i = gwarp;

    float xr[8], attr[8];
    const float* xrp = g_xr + (long long)i * D_IN;
#pragma unroll
    for (int k = 0; k < 8; k++) {
        xr[k]   = xrp[lane + 32 * k];
        attr[k] = att[lane + 32 * k];
    }

    float m[4], d[4], acc[8];

    // ---- self loop (exp(0) = 1 weight) ----
    {
        const float* xlp = g_xl + (long long)i * D_IN;
        float xlv[8], p[4];
#pragma unroll
        for (int k = 0; k < 8; k++) xlv[k] = xlp[lane + 32 * k];
#pragma unroll
        for (int h = 0; h < 4; h++) {
            float z0 = xlv[2 * h] + xr[2 * h];
            float z1 = xlv[2 * h + 1] + xr[2 * h + 1];
            float l0 = z0 > 0.f ? z0 : NEG_SLOPE * z0;
            float l1 = z1 > 0.f ? z1 : NEG_SLOPE * z1;
            float pp = attr[2 * h] * l0 + attr[2 * h + 1] * l1;
#pragma unroll
            for (int off = 16; off > 0; off >>= 1)
                pp += __shfl_xor_sync(0xffffffffu, pp, off);
            p[h] = pp;
        }
#pragma unroll
        for (int h = 0; h < 4; h++) { m[h] = p[h]; d[h] = 1.f; }
#pragma unroll
        for (int k = 0; k < 8; k++) acc[k] = xlv[k];
    }

    // ---- incoming edges (CSR) ----
    const int end = g_incl[i];
    const int start = end - g_cnt[i];
    for (int j = start; j < end; j++) {
        int src = g_srcs[j];
        const float* xlp = g_xl + (long long)src * D_IN;
        float xlv[8], p[4];
#pragma unroll
        for (int k = 0; k < 8; k++) xlv[k] = xlp[lane + 32 * k];
#pragma unroll
        for (int h = 0; h < 4; h++) {
            float z0 = xlv[2 * h] + xr[2 * h];
            float z1 = xlv[2 * h + 1] + xr[2 * h + 1];
            float l0 = z0 > 0.f ? z0 : NEG_SLOPE * z0;
            float l1 = z1 > 0.f ? z1 : NEG_SLOPE * z1;
            float pp = attr[2 * h] * l0 + attr[2 * h + 1] * l1;
#pragma unroll
            for (int off = 16; off > 0; off >>= 1)
                pp += __shfl_xor_sync(0xffffffffu, pp, off);
            p[h] = pp;
        }
        float cw[4], ww[4];
#pragma unroll
        for (int h = 0; h < 4; h++) {
            float mn = fmaxf(m[h], p[h]);
            cw[h] = __expf(m[h] - mn);
            ww[h] = __expf(p[h] - mn);
            d[h] = d[h] * cw[h] + ww[h];
            m[h] = mn;
        }
#pragma unroll
        for (int k = 0; k < 8; k++) {
            int h = k >> 1;
            acc[k] = acc[k] * cw[h] + ww[h] * xlv[k];
        }
    }

    float inv[4];
#pragma unroll
    for (int h = 0; h < 4; h++) inv[h] = 1.f / (d[h] + 1e-16f);

    // channel j = lane (even k), lane+32 (odd k); mean over 4 heads + bias + ELU
    float o0 = 0.25f * (acc[0] * inv[0] + acc[2] * inv[1] +
                        acc[4] * inv[2] + acc[6] * inv[3]) + bias[lane];
    float o1 = 0.25f * (acc[1] * inv[0] + acc[3] * inv[1] +
                        acc[5] * inv[2] + acc[7] * inv[3]) + bias[lane + 32];
    o0 = o0 > 0.f ? o0 : expm1f(o0);
    o1 = o1 > 0.f ? o1 : expm1f(o1);
    out[(long long)i * D_OUT + lane]      = o0;
    out[(long long)i * D_OUT + lane + 32] = o1;
}

// ============================================================
extern "C" void kernel_launch(void* const* d_in, const int* in_sizes, int n_in,
                              void* d_out, int out_size)
{
    const int* ei        = (const int*)d_in[1];
    const float* emb     = (const float*)d_in[2];
    const float* Wl      = (const float*)d_in[3];
    const float* Wr      = (const float*)d_in[4];
    const float* att     = (const float*)d_in[5];
    const float* bias    = (const float*)d_in[6];
    float* out           = (float*)d_out;

    const int E = in_sizes[1] / 2;            // 1,600,000
    const int M = in_sizes[2] / D_IN;         // 100,000

    // 1) linear transforms
    dim3 gg(2, (M + 127) / 128);
    sgemm128<0><<<gg, 256>>>(emb, Wl, M);
    sgemm128<1><<<gg, 256>>>(emb, Wr, M);

    // 2) CSR by dst
    int tb = 256;
    zero_cnt_k<<<(M + tb - 1) / tb, tb>>>(M);
    count_k<<<(E + tb - 1) / tb, tb>>>(ei, E);
    int nb = (M + 1023) / 1024;
    scan1_k<<<nb, 1024>>>(M);
    scan2_k<<<1, 32>>>(nb);
    scan3_k<<<(M + tb - 1) / tb, tb>>>(M);
    scatter_k<<<(E + tb - 1) / tb, tb>>>(ei, E);

    // 3) attention + aggregation (one warp per node)
    int warps_per_block = tb / 32;
    int nblk = (M + warps_per_block - 1) / warps_per_block;
    agg_k<<<nblk, tb>>>(att, bias, out, M);

    (void)n_in; (void)out_size; (void)d_in;
}

// round 4
// speedup vs baseline: 1.4494x; 1.4494x over previous
#include <cuda_runtime.h>
#include <cuda_bf16.h>
#include <cstdint>

#define N_NODE   100000
#define NODE_PAD 100096
#define D_IN     256
#define D_OUT    64
#define E_MAX    1600000
#define NEG_SLOPE 0.2f

// ---- scratch (__device__ globals; no allocation at runtime) ----
__device__ float g_xl[NODE_PAD * D_IN];
__device__ float g_xr[NODE_PAD * D_IN];
__device__ __nv_bfloat16 g_Ahi[NODE_PAD * D_IN];
__device__ __nv_bfloat16 g_Alo[NODE_PAD * D_IN];
__device__ __nv_bfloat16 g_Bhi[512 * 256];   // rows 0-255: Wl^T, 256-511: Wr^T  ([n][k])
__device__ __nv_bfloat16 g_Blo[512 * 256];
__device__ int   g_cnt[N_NODE];
__device__ int   g_incl[N_NODE];
__device__ int   g_cursor[N_NODE];
__device__ int   g_srcs[E_MAX];
__device__ int   g_bsum[256];

// ============================================================
// Prep: fp32 -> bf16 hi/lo split
// ============================================================
__global__ void prepA_k(const float4* __restrict__ emb4, int n4, int np4)
{
    int i = blockIdx.x * blockDim.x + threadIdx.x;
    if (i >= np4) return;
    float4 v = (i < n4) ? emb4[i] : make_float4(0.f, 0.f, 0.f, 0.f);
    __nv_bfloat16 h0 = __float2bfloat16(v.x), h1 = __float2bfloat16(v.y);
    __nv_bfloat16 h2 = __float2bfloat16(v.z), h3 = __float2bfloat16(v.w);
    __nv_bfloat16 l0 = __float2bfloat16(v.x - __bfloat162float(h0));
    __nv_bfloat16 l1 = __float2bfloat16(v.y - __bfloat162float(h1));
    __nv_bfloat16 l2 = __float2bfloat16(v.z - __bfloat162float(h2));
    __nv_bfloat16 l3 = __float2bfloat16(v.w - __bfloat162float(h3));
    __nv_bfloat162* hp = (__nv_bfloat162*)g_Ahi;
    __nv_bfloat162* lp = (__nv_bfloat162*)g_Alo;
    __nv_bfloat162 a; a.x = h0; a.y = h1;
    __nv_bfloat162 b; b.x = h2; b.y = h3;
    hp[2 * i] = a; hp[2 * i + 1] = b;
    a.x = l0; a.y = l1; b.x = l2; b.y = l3;
    lp[2 * i] = a; lp[2 * i + 1] = b;
}

__global__ void prepW_k(const float* __restrict__ Wl, const float* __restrict__ Wr)
{
    int idx = blockIdx.x * blockDim.x + threadIdx.x;   // 512*256
    if (idx >= 512 * 256) return;
    int n = idx >> 8, k = idx & 255;
    float v = (n < 256) ? Wl[k * 256 + n] : Wr[k * 256 + (n - 256)];
    __nv_bfloat16 h = __float2bfloat16(v);
    g_Bhi[idx] = h;
    g_Blo[idx] = __float2bfloat16(v - __bfloat162float(h));
}

// ============================================================
// mma.sync bf16 GEMM: C[NODE_PAD,512] = A x [Wl|Wr]^T (bf16x3 split)
// CTA tile 128(m) x 128(n), 8 warps of 32x64, K staged 32-wide.
// SMEM ld = 40 bf16 (80B) -> conflict-free fragment LDS.
// ============================================================
#define SLD 40

__device__ __forceinline__ void mma16816(float c[4], const uint32_t a[4],
                                         const uint32_t b[2])
{
    asm volatile(
        "mma.sync.aligned.m16n8k16.row.col.f32.bf16.bf16.f32 "
        "{%0,%1,%2,%3}, {%4,%5,%6,%7}, {%8,%9}, {%0,%1,%2,%3};"
        : "+f"(c[0]), "+f"(c[1]), "+f"(c[2]), "+f"(c[3])
        : "r"(a[0]), "r"(a[1]), "r"(a[2]), "r"(a[3]), "r"(b[0]), "r"(b[1]));
}

__device__ __forceinline__ void lda_frag(uint32_t a[4], const __nv_bfloat16* s,
                                         int row0, int kk, int g, int t)
{
    a[0] = *(const uint32_t*)&s[(row0 + g) * SLD + kk + t * 2];
    a[1] = *(const uint32_t*)&s[(row0 + g + 8) * SLD + kk + t * 2];
    a[2] = *(const uint32_t*)&s[(row0 + g) * SLD + kk + t * 2 + 8];
    a[3] = *(const uint32_t*)&s[(row0 + g + 8) * SLD + kk + t * 2 + 8];
}

__device__ __forceinline__ void ldb_frag(uint32_t b[2], const __nv_bfloat16* s,
                                         int n0, int kk, int g, int t)
{
    b[0] = *(const uint32_t*)&s[(n0 + g) * SLD + kk + t * 2];
    b[1] = *(const uint32_t*)&s[(n0 + g) * SLD + kk + t * 2 + 8];
}

__global__ void __launch_bounds__(256, 1)
gemm_mma()
{
    __shared__ __nv_bfloat16 sAh[128 * SLD];
    __shared__ __nv_bfloat16 sAl[128 * SLD];
    __shared__ __nv_bfloat16 sBh[128 * SLD];
    __shared__ __nv_bfloat16 sBl[128 * SLD];

    const int tid = threadIdx.x;
    const int wid = tid >> 5;
    const int lane = tid & 31;
    const int g = lane >> 2;      // group 0..7
    const int t = lane & 3;       // thread-in-group
    const int m0 = blockIdx.y * 128;
    const int n0 = blockIdx.x * 128;
    const int wm = (wid & 3) * 32;   // warp row base within tile
    const int wn = (wid >> 2) * 64;  // warp col base within tile

    float acc[2][8][4];
#pragma unroll
    for (int i = 0; i < 2; i++)
#pragma unroll
        for (int j = 0; j < 8; j++)
#pragma unroll
            for (int q = 0; q < 4; q++) acc[i][j][q] = 0.f;

    for (int kt = 0; kt < 8; kt++) {
        if (kt > 0) __syncthreads();
        // stage k-tile: 128 rows x 32 bf16 per tile; 512 uint4 per tile
#pragma unroll
        for (int i = 0; i < 2; i++) {
            int idx = tid + i * 256;
            int r = idx >> 2, q = idx & 3;
            size_t ga = (size_t)(m0 + r) * 256 + kt * 32 + q * 8;
            size_t gb = (size_t)(n0 + r) * 256 + kt * 32 + q * 8;
            int so = r * SLD + q * 8;
            *(uint4*)&sAh[so] = *(const uint4*)&g_Ahi[ga];
            *(uint4*)&sAl[so] = *(const uint4*)&g_Alo[ga];
            *(uint4*)&sBh[so] = *(const uint4*)&g_Bhi[gb];
            *(uint4*)&sBl[so] = *(const uint4*)&g_Blo[gb];
        }
        __syncthreads();

#pragma unroll
        for (int kk = 0; kk < 32; kk += 16) {
            uint32_t ah[2][4], al[2][4];
            lda_frag(ah[0], sAh, wm, kk, g, t);
            lda_frag(ah[1], sAh, wm + 16, kk, g, t);
            lda_frag(al[0], sAl, wm, kk, g, t);
            lda_frag(al[1], sAl, wm + 16, kk, g, t);
#pragma unroll
            for (int ni = 0; ni < 8; ni++) {
                uint32_t bh[2], bl[2];
                ldb_frag(bh, sBh, wn + ni * 8, kk, g, t);
                ldb_frag(bl, sBl, wn + ni * 8, kk, g, t);
                mma16816(acc[0][ni], ah[0], bh);
                mma16816(acc[1][ni], ah[1], bh);
                mma16816(acc[0][ni], ah[0], bl);
                mma16816(acc[1][ni], ah[1], bl);
                mma16816(acc[0][ni], al[0], bh);
                mma16816(acc[1][ni], al[1], bh);
            }
        }
    }

    // epilogue: c0,c1 -> (row, col..col+1); c2,c3 -> (row+8, col..col+1)
#pragma unroll
    for (int mi = 0; mi < 2; mi++) {
        int row = m0 + wm + 16 * mi + g;
#pragma unroll
        for (int ni = 0; ni < 8; ni++) {
            int nc = n0 + wn + ni * 8 + t * 2;
            float* base = (nc < 256) ? g_xl : g_xr;
            int col = nc & 255;
            float2 v0 = make_float2(acc[mi][ni][0], acc[mi][ni][1]);
            float2 v1 = make_float2(acc[mi][ni][2], acc[mi][ni][3]);
            *(float2*)&base[(size_t)row * 256 + col] = v0;
            *(float2*)&base[(size_t)(row + 8) * 256 + col] = v1;
        }
    }
}

// ============================================================
// CSR construction  (edge_index int32: row 0 = src, row 1 = dst)
// ============================================================
__global__ void zero_cnt_k(int M)
{
    int i = blockIdx.x * blockDim.x + threadIdx.x;
    if (i < M) g_cnt[i] = 0;
}

__global__ void count_k(const int* __restrict__ ei, int E)
{
    int e = blockIdx.x * blockDim.x + threadIdx.x;
    if (e < E) atomicAdd(&g_cnt[ei[E + e]], 1);
}

__global__ void scan1_k(int M)
{
    __shared__ int s[1024];
    int gi = blockIdx.x * 1024 + threadIdx.x;
    int v = (gi < M) ? g_cnt[gi] : 0;
    s[threadIdx.x] = v;
    __syncthreads();
#pragma unroll
    for (int off = 1; off < 1024; off <<= 1) {
        int tv = (threadIdx.x >= off) ? s[threadIdx.x - off] : 0;
        __syncthreads();
        s[threadIdx.x] += tv;
        __syncthreads();
    }
    if (gi < M) g_incl[gi] = s[threadIdx.x];
    if (threadIdx.x == 1023) g_bsum[blockIdx.x] = s[1023];
}

__global__ void scan2_k(int nb)
{
    if (threadIdx.x == 0 && blockIdx.x == 0) {
        int run = 0;
        for (int b = 0; b < nb; b++) { int tv = g_bsum[b]; g_bsum[b] = run; run += tv; }
    }
}

__global__ void scan3_k(int M)
{
    int i = blockIdx.x * blockDim.x + threadIdx.x;
    if (i < M) {
        int incl = g_incl[i] + g_bsum[i >> 10];
        g_incl[i] = incl;
        g_cursor[i] = incl - g_cnt[i];
    }
}

__global__ void scatter_k(const int* __restrict__ ei, int E)
{
    int e = blockIdx.x * blockDim.x + threadIdx.x;
    if (e < E) {
        int d = ei[E + e];
        int pos = atomicAdd(&g_cursor[d], 1);
        g_srcs[pos] = ei[e];
    }
}

// ============================================================
// Per-node GATv2 attention + aggregation, one warp per dst node.
// Online softmax, single pass. Lane owns channels c = lane + 32k.
// ============================================================
__global__ void __launch_bounds__(256)
agg_k(const float* __restrict__ att, const float* __restrict__ bias,
      float* __restrict__ out, int M)
{
    const int gwarp = (blockIdx.x * blockDim.x + threadIdx.x) >> 5;
    const int lane = threadIdx.x & 31;
    if (gwarp >= M) return;
    const int i = gwarp;

    float xr[8], attr[8];
    const float* xrp = g_xr + (size_t)i * D_IN;
#pragma unroll
    for (int k = 0; k < 8; k++) {
        xr[k]   = xrp[lane + 32 * k];
        attr[k] = att[lane + 32 * k];
    }

    float m[4], d[4], acc[8];
    {
        const float* xlp = g_xl + (size_t)i * D_IN;
        float xlv[8], p[4];
#pragma unroll
        for (int k = 0; k < 8; k++) xlv[k] = xlp[lane + 32 * k];
#pragma unroll
        for (int h = 0; h < 4; h++) {
            float z0 = xlv[2 * h] + xr[2 * h];
            float z1 = xlv[2 * h + 1] + xr[2 * h + 1];
            float l0 = z0 > 0.f ? z0 : NEG_SLOPE * z0;
            float l1 = z1 > 0.f ? z1 : NEG_SLOPE * z1;
            float pp = attr[2 * h] * l0 + attr[2 * h + 1] * l1;
#pragma unroll
            for (int off = 16; off > 0; off >>= 1)
                pp += __shfl_xor_sync(0xffffffffu, pp, off);
            p[h] = pp;
        }
#pragma unroll
        for (int h = 0; h < 4; h++) { m[h] = p[h]; d[h] = 1.f; }
#pragma unroll
        for (int k = 0; k < 8; k++) acc[k] = xlv[k];
    }

    const int end = g_incl[i];
    const int start = end - g_cnt[i];
    for (int j = start; j < end; j++) {
        int src = g_srcs[j];
        const float* xlp = g_xl + (size_t)src * D_IN;
        float xlv[8], p[4];
#pragma unroll
        for (int k = 0; k < 8; k++) xlv[k] = xlp[lane + 32 * k];
#pragma unroll
        for (int h = 0; h < 4; h++) {
            float z0 = xlv[2 * h] + xr[2 * h];
            float z1 = xlv[2 * h + 1] + xr[2 * h + 1];
            float l0 = z0 > 0.f ? z0 : NEG_SLOPE * z0;
            float l1 = z1 > 0.f ? z1 : NEG_SLOPE * z1;
            float pp = attr[2 * h] * l0 + attr[2 * h + 1] * l1;
#pragma unroll
            for (int off = 16; off > 0; off >>= 1)
                pp += __shfl_xor_sync(0xffffffffu, pp, off);
            p[h] = pp;
        }
        float cw[4], ww[4];
#pragma unroll
        for (int h = 0; h < 4; h++) {
            float mn = fmaxf(m[h], p[h]);
            cw[h] = __expf(m[h] - mn);
            ww[h] = __expf(p[h] - mn);
            d[h] = d[h] * cw[h] + ww[h];
            m[h] = mn;
        }
#pragma unroll
        for (int k = 0; k < 8; k++) {
            int h = k >> 1;
            acc[k] = acc[k] * cw[h] + ww[h] * xlv[k];
        }
    }

    float inv[4];
#pragma unroll
    for (int h = 0; h < 4; h++) inv[h] = 1.f / (d[h] + 1e-16f);

    float o0 = 0.25f * (acc[0] * inv[0] + acc[2] * inv[1] +
                        acc[4] * inv[2] + acc[6] * inv[3]) + bias[lane];
    float o1 = 0.25f * (acc[1] * inv[0] + acc[3] * inv[1] +
                        acc[5] * inv[2] + acc[7] * inv[3]) + bias[lane + 32];
    o0 = o0 > 0.f ? o0 : expm1f(o0);
    o1 = o1 > 0.f ? o1 : expm1f(o1);
    out[(size_t)i * D_OUT + lane]      = o0;
    out[(size_t)i * D_OUT + lane + 32] = o1;
}

// ============================================================
extern "C" void kernel_launch(void* const* d_in, const int* in_sizes, int n_in,
                              void* d_out, int out_size)
{
    const int* ei        = (const int*)d_in[1];
    const float* emb     = (const float*)d_in[2];
    const float* Wl      = (const float*)d_in[3];
    const float* Wr      = (const float*)d_in[4];
    const float* att     = (const float*)d_in[5];
    const float* bias    = (const float*)d_in[6];
    float* out           = (float*)d_out;

    const int E = in_sizes[1] / 2;         // 1,600,000
    const int M = in_sizes[2] / D_IN;      // 100,000
    const int T = (M + 127) / 128;         // 782 row tiles (NODE_PAD/128)
    const int MP = T * 128;

    // 1) bf16 hi/lo prep + mma.sync GEMM (xl and xr in one pass)
    int n4 = M * 64, np4 = MP * 64;
    prepA_k<<<(np4 + 255) / 256, 256>>>((const float4*)emb, n4, np4);
    prepW_k<<<512, 256>>>(Wl, Wr);
    gemm_mma<<<dim3(4, T), 256>>>();

    // 2) CSR by dst
    int tb = 256;
    zero_cnt_k<<<(M + tb - 1) / tb, tb>>>(M);
    count_k<<<(E + tb - 1) / tb, tb>>>(ei, E);
    int nb = (M + 1023) / 1024;
    scan1_k<<<nb, 1024>>>(M);
    scan2_k<<<1, 32>>>(nb);
    scan3_k<<<(M + tb - 1) / tb, tb>>>(M);
    scatter_k<<<(E + tb - 1) / tb, tb>>>(ei, E);

    // 3) attention + aggregation (one warp per node)
    int nblk = (M + 7) / 8;
    agg_k<<<nblk, 256>>>(att, bias, out, M);

    (void)n_in; (void)out_size;
}

// round 5
// speedup vs baseline: 1.9454x; 1.3423x over previous
#include <cuda_runtime.h>
#include <cuda_bf16.h>
#include <cstdint>

#define N_NODE   100000
#define NODE_PAD 100096
#define D_IN     256
#define D_OUT    64
#define E_MAX    1600000
#define NEG_SLOPE 0.2f
#define SLD 40   // smem row stride in bf16 elems (80B)

// ---- scratch (__device__ globals; no allocation at runtime) ----
__device__ float g_xl[NODE_PAD * D_IN];
__device__ float g_xr[NODE_PAD * D_IN];
__device__ __nv_bfloat16 g_Ahi[NODE_PAD * D_IN];
__device__ __nv_bfloat16 g_Alo[NODE_PAD * D_IN];
__device__ __nv_bfloat16 g_Bhi[512 * 256];   // rows 0-255: Wl^T, 256-511: Wr^T ([n][k])
__device__ __nv_bfloat16 g_Blo[512 * 256];
__device__ int   g_cnt[N_NODE];
__device__ int   g_incl[N_NODE];
__device__ int   g_cursor[N_NODE];
__device__ int   g_srcs[E_MAX];
__device__ int   g_bsum[256];

// ============================================================
// Prep: fp32 -> bf16 hi/lo split
// ============================================================
__global__ void prepA_k(const float4* __restrict__ emb4, int n4, int np4)
{
    int i = blockIdx.x * blockDim.x + threadIdx.x;
    if (i >= np4) return;
    float4 v = (i < n4) ? emb4[i] : make_float4(0.f, 0.f, 0.f, 0.f);
    __nv_bfloat16 h0 = __float2bfloat16(v.x), h1 = __float2bfloat16(v.y);
    __nv_bfloat16 h2 = __float2bfloat16(v.z), h3 = __float2bfloat16(v.w);
    __nv_bfloat16 l0 = __float2bfloat16(v.x - __bfloat162float(h0));
    __nv_bfloat16 l1 = __float2bfloat16(v.y - __bfloat162float(h1));
    __nv_bfloat16 l2 = __float2bfloat16(v.z - __bfloat162float(h2));
    __nv_bfloat16 l3 = __float2bfloat16(v.w - __bfloat162float(h3));
    __nv_bfloat162* hp = (__nv_bfloat162*)g_Ahi;
    __nv_bfloat162* lp = (__nv_bfloat162*)g_Alo;
    __nv_bfloat162 a; a.x = h0; a.y = h1;
    __nv_bfloat162 b; b.x = h2; b.y = h3;
    hp[2 * i] = a; hp[2 * i + 1] = b;
    a.x = l0; a.y = l1; b.x = l2; b.y = l3;
    lp[2 * i] = a; lp[2 * i + 1] = b;
}

__global__ void prepW_k(const float* __restrict__ Wl, const float* __restrict__ Wr)
{
    int idx = blockIdx.x * blockDim.x + threadIdx.x;   // 512*256
    if (idx >= 512 * 256) return;
    int n = idx >> 8, k = idx & 255;
    float v = (n < 256) ? Wl[k * 256 + n] : Wr[k * 256 + (n - 256)];
    __nv_bfloat16 h = __float2bfloat16(v);
    g_Bhi[idx] = h;
    g_Blo[idx] = __float2bfloat16(v - __bfloat162float(h));
}

// ============================================================
// mma.sync bf16 GEMM, cp.async double-buffered, ldmatrix frags.
// C[NODE_PAD,512] = A x [Wl|Wr]^T (bf16x3: AhBh + AhBl + AlBh)
// CTA 128x128, 8 warps of 32x64, K staged 32-wide.
// ============================================================
__device__ __forceinline__ void mma16816(float c[4], const uint32_t a[4],
                                         const uint32_t b0, const uint32_t b1)
{
    asm volatile(
        "mma.sync.aligned.m16n8k16.row.col.f32.bf16.bf16.f32 "
        "{%0,%1,%2,%3}, {%4,%5,%6,%7}, {%8,%9}, {%0,%1,%2,%3};"
        : "+f"(c[0]), "+f"(c[1]), "+f"(c[2]), "+f"(c[3])
        : "r"(a[0]), "r"(a[1]), "r"(a[2]), "r"(a[3]), "r"(b0), "r"(b1));
}

__device__ __forceinline__ void ldsm4(uint32_t r[4], uint32_t addr)
{
    asm volatile("ldmatrix.sync.aligned.m8n8.x4.shared.b16 {%0,%1,%2,%3}, [%4];"
                 : "=r"(r[0]), "=r"(r[1]), "=r"(r[2]), "=r"(r[3]) : "r"(addr));
}

__device__ __forceinline__ void cpa16(uint32_t dst, const void* src)
{
    asm volatile("cp.async.ca.shared.global [%0], [%1], 16;"
                 :: "r"(dst), "l"(src));
}

#define TILE_B 10240           // bytes per tile (128*SLD*2)
#define STAGE_B (4 * TILE_B)   // Ah, Al, Bh, Bl

__global__ void __launch_bounds__(256, 1)
gemm_mma()
{
    extern __shared__ __align__(16) char smem[];
    uint32_t sb;
    asm("{ .reg .u64 t; cvta.to.shared.u64 t, %1; cvt.u32.u64 %0, t; }"
        : "=r"(sb) : "l"(smem));

    const int tid = threadIdx.x;
    const int wid = tid >> 5;
    const int lane = tid & 31;
    const int g = lane >> 2;
    const int t = lane & 3;
    const int m0 = blockIdx.y * 128;
    const int n0 = blockIdx.x * 128;
    const int wm = (wid & 3) * 32;
    const int wn = (wid >> 2) * 64;

    // staging offsets for this thread (2 chunks)
    int r0i = tid >> 2, q0i = tid & 3;
    int r1i = (tid + 256) >> 2, q1i = tid & 3;

    float acc[2][8][4];
#pragma unroll
    for (int i = 0; i < 2; i++)
#pragma unroll
        for (int j = 0; j < 8; j++)
#pragma unroll
            for (int q = 0; q < 4; q++) acc[i][j][q] = 0.f;

    auto stage_load = [&](int s, int kt) {
        uint32_t st = sb + s * STAGE_B;
#pragma unroll
        for (int i = 0; i < 2; i++) {
            int r = i ? r1i : r0i, q = i ? q1i : q0i;
            size_t ga = (size_t)(m0 + r) * 256 + kt * 32 + q * 8;
            size_t gb = (size_t)(n0 + r) * 256 + kt * 32 + q * 8;
            uint32_t so = (uint32_t)(r * SLD + q * 8) * 2;
            cpa16(st + so,              g_Ahi + ga);
            cpa16(st + TILE_B + so,     g_Alo + ga);
            cpa16(st + 2 * TILE_B + so, g_Bhi + gb);
            cpa16(st + 3 * TILE_B + so, g_Blo + gb);
        }
        asm volatile("cp.async.commit_group;" ::: "memory");
    };

    stage_load(0, 0);

    for (int kt = 0; kt < 8; kt++) {
        if (kt < 7) {
            stage_load((kt + 1) & 1, kt + 1);
            asm volatile("cp.async.wait_group 1;" ::: "memory");
        } else {
            asm volatile("cp.async.wait_group 0;" ::: "memory");
        }
        __syncthreads();

        uint32_t st = sb + (kt & 1) * STAGE_B;
        uint32_t bAh = st, bAl = st + TILE_B;
        uint32_t bBh = st + 2 * TILE_B, bBl = st + 3 * TILE_B;

#pragma unroll
        for (int kk = 0; kk < 32; kk += 16) {
            // A frags: row = wm + mi*16 + (lane&15); kchunk = kk + ((lane>>4)*8)
            uint32_t ah[2][4], al[2][4];
            int arow = (lane & 15);
            int akch = kk + ((lane >> 4) << 3);
#pragma unroll
            for (int mi = 0; mi < 2; mi++) {
                uint32_t ao = (uint32_t)((wm + mi * 16 + arow) * SLD + akch) * 2;
                ldsm4(ah[mi], bAh + ao);
                ldsm4(al[mi], bAl + ao);
            }
            // B frags: 2 ni per ldsm.x4
            int brow = (lane & 7) + ((lane >> 4) << 3);
            int bkch = kk + (((lane >> 3) & 1) << 3);
#pragma unroll
            for (int npi = 0; npi < 4; npi++) {
                uint32_t bo =
                    (uint32_t)((wn + npi * 16 + brow) * SLD + bkch) * 2;
                uint32_t bh[4], bl[4];
                ldsm4(bh, bBh + bo);
                ldsm4(bl, bBl + bo);
                int n0i = npi * 2, n1i = npi * 2 + 1;
                mma16816(acc[0][n0i], ah[0], bh[0], bh[1]);
                mma16816(acc[1][n0i], ah[1], bh[0], bh[1]);
                mma16816(acc[0][n1i], ah[0], bh[2], bh[3]);
                mma16816(acc[1][n1i], ah[1], bh[2], bh[3]);
                mma16816(acc[0][n0i], ah[0], bl[0], bl[1]);
                mma16816(acc[1][n0i], ah[1], bl[0], bl[1]);
                mma16816(acc[0][n1i], ah[0], bl[2], bl[3]);
                mma16816(acc[1][n1i], ah[1], bl[2], bl[3]);
                mma16816(acc[0][n0i], al[0], bh[0], bh[1]);
                mma16816(acc[1][n0i], al[1], bh[0], bh[1]);
                mma16816(acc[0][n1i], al[0], bh[2], bh[3]);
                mma16816(acc[1][n1i], al[1], bh[2], bh[3]);
            }
        }
        __syncthreads();
    }

    // epilogue
#pragma unroll
    for (int mi = 0; mi < 2; mi++) {
        int row = m0 + wm + 16 * mi + g;
#pragma unroll
        for (int ni = 0; ni < 8; ni++) {
            int nc = n0 + wn + ni * 8 + t * 2;
            float* base = (nc < 256) ? g_xl : g_xr;
            int col = nc & 255;
            *(float2*)&base[(size_t)row * 256 + col] =
                make_float2(acc[mi][ni][0], acc[mi][ni][1]);
            *(float2*)&base[(size_t)(row + 8) * 256 + col] =
                make_float2(acc[mi][ni][2], acc[mi][ni][3]);
        }
    }
}

// ============================================================
// CSR construction  (edge_index int32: row 0 = src, row 1 = dst)
// ============================================================
__global__ void zero_cnt_k(int M)
{
    int i = blockIdx.x * blockDim.x + threadIdx.x;
    if (i < M) g_cnt[i] = 0;
}

__global__ void count_k(const int* __restrict__ ei, int E)
{
    int e = blockIdx.x * blockDim.x + threadIdx.x;
    if (e < E) atomicAdd(&g_cnt[ei[E + e]], 1);
}

__global__ void scan1_k(int M)
{
    __shared__ int s[1024];
    int gi = blockIdx.x * 1024 + threadIdx.x;
    int v = (gi < M) ? g_cnt[gi] : 0;
    s[threadIdx.x] = v;
    __syncthreads();
#pragma unroll
    for (int off = 1; off < 1024; off <<= 1) {
        int tv = (threadIdx.x >= off) ? s[threadIdx.x - off] : 0;
        __syncthreads();
        s[threadIdx.x] += tv;
        __syncthreads();
    }
    if (gi < M) g_incl[gi] = s[threadIdx.x];
    if (threadIdx.x == 1023) g_bsum[blockIdx.x] = s[1023];
}

__global__ void scan2_k(int nb)
{
    if (threadIdx.x == 0 && blockIdx.x == 0) {
        int run = 0;
        for (int b = 0; b < nb; b++) { int tv = g_bsum[b]; g_bsum[b] = run; run += tv; }
    }
}

__global__ void scan3_k(int M)
{
    int i = blockIdx.x * blockDim.x + threadIdx.x;
    if (i < M) {
        int incl = g_incl[i] + g_bsum[i >> 10];
        g_incl[i] = incl;
        g_cursor[i] = incl - g_cnt[i];
    }
}

__global__ void scatter_k(const int* __restrict__ ei, int E)
{
    int e = blockIdx.x * blockDim.x + threadIdx.x;
    if (e < E) {
        int d = ei[E + e];
        int pos = atomicAdd(&g_cursor[d], 1);
        g_srcs[pos] = ei[e];
    }
}

// ============================================================
// GATv2 attention + aggregation, one warp per dst node.
// Lane owns float4 channels [4l..4l+3] (head l>>4) and
// [128+4l..128+4l+3] (head 2+(l>>4)). 16-lane segmented reductions.
// ============================================================
__device__ __forceinline__ float leaky4dot(float4 xl, float4 xr, float4 at)
{
    float z0 = xl.x + xr.x, z1 = xl.y + xr.y, z2 = xl.z + xr.z, z3 = xl.w + xr.w;
    float l0 = z0 > 0.f ? z0 : NEG_SLOPE * z0;
    float l1 = z1 > 0.f ? z1 : NEG_SLOPE * z1;
    float l2 = z2 > 0.f ? z2 : NEG_SLOPE * z2;
    float l3 = z3 > 0.f ? z3 : NEG_SLOPE * z3;
    return at.x * l0 + at.y * l1 + at.z * l2 + at.w * l3;
}

__device__ __forceinline__ float red16(float v)
{
#pragma unroll
    for (int off = 8; off > 0; off >>= 1)
        v += __shfl_xor_sync(0xffffffffu, v, off);
    return v;
}

__global__ void __launch_bounds__(256)
agg_k(const float* __restrict__ att, const float* __restrict__ bias,
      float* __restrict__ out, int M)
{
    const int gwarp = (blockIdx.x * blockDim.x + threadIdx.x) >> 5;
    const int lane = threadIdx.x & 31;
    if (gwarp >= M) return;
    const int i = gwarp;
    const int l4 = lane * 4;

    const float* xrp = g_xl;  // placate compiler, reassigned below
    xrp = g_xr + (size_t)i * D_IN;
    float4 xrA = *(const float4*)&xrp[l4];
    float4 xrB = *(const float4*)&xrp[128 + l4];
    float4 atA = *(const float4*)&att[l4];
    float4 atB = *(const float4*)&att[128 + l4];

    float mA, dA, mB, dB;
    float4 accA, accB;

    // ---- self loop ----
    {
        const float* xlp = g_xl + (size_t)i * D_IN;
        float4 xlA = *(const float4*)&xlp[l4];
        float4 xlB = *(const float4*)&xlp[128 + l4];
        mA = red16(leaky4dot(xlA, xrA, atA));
        mB = red16(leaky4dot(xlB, xrB, atB));
        dA = 1.f; dB = 1.f;
        accA = xlA; accB = xlB;
    }

    const int end = g_incl[i];
    int j = end - g_cnt[i];

    if (j < end) {
        int src = g_srcs[j];
        const float* xlp = g_xl + (size_t)src * D_IN;
        float4 nA = *(const float4*)&xlp[l4];
        float4 nB = *(const float4*)&xlp[128 + l4];
        for (; j < end; j++) {
            float4 xlA = nA, xlB = nB;
            if (j + 1 < end) {
                int s2 = g_srcs[j + 1];
                const float* xp = g_xl + (size_t)s2 * D_IN;
                nA = *(const float4*)&xp[l4];
                nB = *(const float4*)&xp[128 + l4];
            }
            float pA = red16(leaky4dot(xlA, xrA, atA));
            float pB = red16(leaky4dot(xlB, xrB, atB));

            float mnA = fmaxf(mA, pA);
            float cwA = __expf(mA - mnA), wwA = __expf(pA - mnA);
            dA = dA * cwA + wwA; mA = mnA;
            accA.x = accA.x * cwA + wwA * xlA.x;
            accA.y = accA.y * cwA + wwA * xlA.y;
            accA.z = accA.z * cwA + wwA * xlA.z;
            accA.w = accA.w * cwA + wwA * xlA.w;

            float mnB = fmaxf(mB, pB);
            float cwB = __expf(mB - mnB), wwB = __expf(pB - mnB);
            dB = dB * cwB + wwB; mB = mnB;
            accB.x = accB.x * cwB + wwB * xlB.x;
            accB.y = accB.y * cwB + wwB * xlB.y;
            accB.z = accB.z * cwB + wwB * xlB.z;
            accB.w = accB.w * cwB + wwB * xlB.w;
        }
    }

    float invA = 1.f / (dA + 1e-16f);
    float invB = 1.f / (dB + 1e-16f);
    float z0 = accA.x * invA + accB.x * invB;
    float z1 = accA.y * invA + accB.y * invB;
    float z2 = accA.z * invA + accB.z * invB;
    float z3 = accA.w * invA + accB.w * invB;
    z0 += __shfl_xor_sync(0xffffffffu, z0, 16);
    z1 += __shfl_xor_sync(0xffffffffu, z1, 16);
    z2 += __shfl_xor_sync(0xffffffffu, z2, 16);
    z3 += __shfl_xor_sync(0xffffffffu, z3, 16);

    if (lane < 16) {
        float o0 = 0.25f * z0 + bias[l4];
        float o1 = 0.25f * z1 + bias[l4 + 1];
        float o2 = 0.25f * z2 + bias[l4 + 2];
        float o3 = 0.25f * z3 + bias[l4 + 3];
        o0 = o0 > 0.f ? o0 : expm1f(o0);
        o1 = o1 > 0.f ? o1 : expm1f(o1);
        o2 = o2 > 0.f ? o2 : expm1f(o2);
        o3 = o3 > 0.f ? o3 : expm1f(o3);
        *(float4*)&out[(size_t)i * D_OUT + l4] = make_float4(o0, o1, o2, o3);
    }
}

// ============================================================
extern "C" void kernel_launch(void* const* d_in, const int* in_sizes, int n_in,
                              void* d_out, int out_size)
{
    const int* ei        = (const int*)d_in[1];
    const float* emb     = (const float*)d_in[2];
    const float* Wl      = (const float*)d_in[3];
    const float* Wr      = (const float*)d_in[4];
    const float* att     = (const float*)d_in[5];
    const float* bias    = (const float*)d_in[6];
    float* out           = (float*)d_out;

    const int E = in_sizes[1] / 2;         // 1,600,000
    const int M = in_sizes[2] / D_IN;      // 100,000
    const int T = (M + 127) / 128;         // 782 row tiles
    const int MP = T * 128;

    const int GEMM_SMEM = 2 * STAGE_B;     // 81920 B
    static int smem_set = 0;
    if (!smem_set) {
        cudaFuncSetAttribute(gemm_mma, cudaFuncAttributeMaxDynamicSharedMemorySize,
                             GEMM_SMEM);
        smem_set = 1;
    }

    // 1) bf16 hi/lo prep + mma.sync GEMM (xl and xr in one pass)
    int n4 = M * 64, np4 = MP * 64;
    prepA_k<<<(np4 + 255) / 256, 256>>>((const float4*)emb, n4, np4);
    prepW_k<<<512, 256>>>(Wl, Wr);
    gemm_mma<<<dim3(4, T), 256, GEMM_SMEM>>>();

    // 2) CSR by dst
    int tb = 256;
    zero_cnt_k<<<(M + tb - 1) / tb, tb>>>(M);
    count_k<<<(E + tb - 1) / tb, tb>>>(ei, E);
    int nb = (M + 1023) / 1024;
    scan1_k<<<nb, 1024>>>(M);
    scan2_k<<<1, 32>>>(nb);
    scan3_k<<<(M + tb - 1) / tb, tb>>>(M);
    scatter_k<<<(E + tb - 1) / tb, tb>>>(ei, E);

    // 3) attention + aggregation (one warp per node)
    int nblk = (M + 7) / 8;
    agg_k<<<nblk, 256>>>(att, bias, out, M);

    (void)n_in; (void)out_size;
}

// round 6
// speedup vs baseline: 1.9891x; 1.0224x over previous
#include <cuda_runtime.h>
#include <cuda_bf16.h>
#include <cstdint>

#define N_NODE   100000
#define NODE_PAD 100096
#define D_IN     256
#define D_OUT    64
#define E_MAX    1600000
#define NEG_SLOPE 0.2f
#define SLD 40   // smem row stride in bf16 elems (80B)

// ---- scratch (__device__ globals; no allocation at runtime) ----
__device__ float g_xl[NODE_PAD * D_IN];
__device__ float g_xr[NODE_PAD * D_IN];
__device__ __nv_bfloat16 g_Ahi[NODE_PAD * D_IN];
__device__ __nv_bfloat16 g_Alo[NODE_PAD * D_IN];
__device__ __nv_bfloat16 g_Bhi[512 * 256];   // rows 0-255: Wl^T, 256-511: Wr^T ([n][k])
__device__ __nv_bfloat16 g_Blo[512 * 256];
__device__ int   g_cnt[N_NODE];
__device__ int   g_incl[N_NODE];
__device__ int   g_cursor[N_NODE];
__device__ int   g_srcs[E_MAX];
__device__ int   g_bsum[256];

// ============================================================
// Prep: fp32 -> bf16 hi/lo split
// ============================================================
__global__ void prepA_k(const float4* __restrict__ emb4, int n4, int np4)
{
    int i = blockIdx.x * blockDim.x + threadIdx.x;
    if (i >= np4) return;
    float4 v = (i < n4) ? emb4[i] : make_float4(0.f, 0.f, 0.f, 0.f);
    __nv_bfloat16 h0 = __float2bfloat16(v.x), h1 = __float2bfloat16(v.y);
    __nv_bfloat16 h2 = __float2bfloat16(v.z), h3 = __float2bfloat16(v.w);
    __nv_bfloat16 l0 = __float2bfloat16(v.x - __bfloat162float(h0));
    __nv_bfloat16 l1 = __float2bfloat16(v.y - __bfloat162float(h1));
    __nv_bfloat16 l2 = __float2bfloat16(v.z - __bfloat162float(h2));
    __nv_bfloat16 l3 = __float2bfloat16(v.w - __bfloat162float(h3));
    __nv_bfloat162* hp = (__nv_bfloat162*)g_Ahi;
    __nv_bfloat162* lp = (__nv_bfloat162*)g_Alo;
    __nv_bfloat162 a; a.x = h0; a.y = h1;
    __nv_bfloat162 b; b.x = h2; b.y = h3;
    hp[2 * i] = a; hp[2 * i + 1] = b;
    a.x = l0; a.y = l1; b.x = l2; b.y = l3;
    lp[2 * i] = a; lp[2 * i + 1] = b;
}

__global__ void prepW_k(const float* __restrict__ Wl, const float* __restrict__ Wr)
{
    int idx = blockIdx.x * blockDim.x + threadIdx.x;   // 512*256
    if (idx >= 512 * 256) return;
    int n = idx >> 8, k = idx & 255;
    float v = (n < 256) ? Wl[k * 256 + n] : Wr[k * 256 + (n - 256)];
    __nv_bfloat16 h = __float2bfloat16(v);
    g_Bhi[idx] = h;
    g_Blo[idx] = __float2bfloat16(v - __bfloat162float(h));
}

// ============================================================
// mma.sync bf16 GEMM, cp.async double-buffered, ldmatrix frags.
// C[NODE_PAD,512] = A x [Wl|Wr]^T (bf16x3: AhBh + AhBl + AlBh)
// CTA 128x128, 8 warps of 32x64, K staged 32-wide.
// ============================================================
__device__ __forceinline__ void mma16816(float c[4], const uint32_t a[4],
                                         const uint32_t b0, const uint32_t b1)
{
    asm volatile(
        "mma.sync.aligned.m16n8k16.row.col.f32.bf16.bf16.f32 "
        "{%0,%1,%2,%3}, {%4,%5,%6,%7}, {%8,%9}, {%0,%1,%2,%3};"
        : "+f"(c[0]), "+f"(c[1]), "+f"(c[2]), "+f"(c[3])
        : "r"(a[0]), "r"(a[1]), "r"(a[2]), "r"(a[3]), "r"(b0), "r"(b1));
}

__device__ __forceinline__ void ldsm4(uint32_t r[4], uint32_t addr)
{
    asm volatile("ldmatrix.sync.aligned.m8n8.x4.shared.b16 {%0,%1,%2,%3}, [%4];"
                 : "=r"(r[0]), "=r"(r[1]), "=r"(r[2]), "=r"(r[3]) : "r"(addr));
}

__device__ __forceinline__ void cpa16(uint32_t dst, const void* src)
{
    asm volatile("cp.async.ca.shared.global [%0], [%1], 16;"
                 :: "r"(dst), "l"(src));
}

#define TILE_B 10240           // bytes per tile (128*SLD*2)
#define STAGE_B (4 * TILE_B)   // Ah, Al, Bh, Bl

__global__ void __launch_bounds__(256, 1)
gemm_mma()
{
    extern __shared__ __align__(16) char smem[];
    uint32_t sb;
    asm("{ .reg .u64 t; cvta.to.shared.u64 t, %1; cvt.u32.u64 %0, t; }"
        : "=r"(sb) : "l"(smem));

    const int tid = threadIdx.x;
    const int wid = tid >> 5;
    const int lane = tid & 31;
    const int g = lane >> 2;
    const int t = lane & 3;
    const int m0 = blockIdx.y * 128;
    const int n0 = blockIdx.x * 128;
    const int wm = (wid & 3) * 32;
    const int wn = (wid >> 2) * 64;

    int r0i = tid >> 2, q0i = tid & 3;
    int r1i = (tid + 256) >> 2, q1i = tid & 3;

    float acc[2][8][4];
#pragma unroll
    for (int i = 0; i < 2; i++)
#pragma unroll
        for (int j = 0; j < 8; j++)
#pragma unroll
            for (int q = 0; q < 4; q++) acc[i][j][q] = 0.f;

    auto stage_load = [&](int s, int kt) {
        uint32_t st = sb + s * STAGE_B;
#pragma unroll
        for (int i = 0; i < 2; i++) {
            int r = i ? r1i : r0i, q = i ? q1i : q0i;
            size_t ga = (size_t)(m0 + r) * 256 + kt * 32 + q * 8;
            size_t gb = (size_t)(n0 + r) * 256 + kt * 32 + q * 8;
            uint32_t so = (uint32_t)(r * SLD + q * 8) * 2;
            cpa16(st + so,              g_Ahi + ga);
            cpa16(st + TILE_B + so,     g_Alo + ga);
            cpa16(st + 2 * TILE_B + so, g_Bhi + gb);
            cpa16(st + 3 * TILE_B + so, g_Blo + gb);
        }
        asm volatile("cp.async.commit_group;" ::: "memory");
    };

    stage_load(0, 0);

    for (int kt = 0; kt < 8; kt++) {
        if (kt < 7) {
            stage_load((kt + 1) & 1, kt + 1);
            asm volatile("cp.async.wait_group 1;" ::: "memory");
        } else {
            asm volatile("cp.async.wait_group 0;" ::: "memory");
        }
        __syncthreads();

        uint32_t st = sb + (kt & 1) * STAGE_B;
        uint32_t bAh = st, bAl = st + TILE_B;
        uint32_t bBh = st + 2 * TILE_B, bBl = st + 3 * TILE_B;

#pragma unroll
        for (int kk = 0; kk < 32; kk += 16) {
            uint32_t ah[2][4], al[2][4];
            int arow = (lane & 15);
            int akch = kk + ((lane >> 4) << 3);
#pragma unroll
            for (int mi = 0; mi < 2; mi++) {
                uint32_t ao = (uint32_t)((wm + mi * 16 + arow) * SLD + akch) * 2;
                ldsm4(ah[mi], bAh + ao);
                ldsm4(al[mi], bAl + ao);
            }
            int brow = (lane & 7) + ((lane >> 4) << 3);
            int bkch = kk + (((lane >> 3) & 1) << 3);
#pragma unroll
            for (int npi = 0; npi < 4; npi++) {
                uint32_t bo =
                    (uint32_t)((wn + npi * 16 + brow) * SLD + bkch) * 2;
                uint32_t bh[4], bl[4];
                ldsm4(bh, bBh + bo);
                ldsm4(bl, bBl + bo);
                int n0i = npi * 2, n1i = npi * 2 + 1;
                mma16816(acc[0][n0i], ah[0], bh[0], bh[1]);
                mma16816(acc[1][n0i], ah[1], bh[0], bh[1]);
                mma16816(acc[0][n1i], ah[0], bh[2], bh[3]);
                mma16816(acc[1][n1i], ah[1], bh[2], bh[3]);
                mma16816(acc[0][n0i], ah[0], bl[0], bl[1]);
                mma16816(acc[1][n0i], ah[1], bl[0], bl[1]);
                mma16816(acc[0][n1i], ah[0], bl[2], bl[3]);
                mma16816(acc[1][n1i], ah[1], bl[2], bl[3]);
                mma16816(acc[0][n0i], al[0], bh[0], bh[1]);
                mma16816(acc[1][n0i], al[1], bh[0], bh[1]);
                mma16816(acc[0][n1i], al[0], bh[2], bh[3]);
                mma16816(acc[1][n1i], al[1], bh[2], bh[3]);
            }
        }
        __syncthreads();
    }

#pragma unroll
    for (int mi = 0; mi < 2; mi++) {
        int row = m0 + wm + 16 * mi + g;
#pragma unroll
        for (int ni = 0; ni < 8; ni++) {
            int nc = n0 + wn + ni * 8 + t * 2;
            float* base = (nc < 256) ? g_xl : g_xr;
            int col = nc & 255;
            *(float2*)&base[(size_t)row * 256 + col] =
                make_float2(acc[mi][ni][0], acc[mi][ni][1]);
            *(float2*)&base[(size_t)(row + 8) * 256 + col] =
                make_float2(acc[mi][ni][2], acc[mi][ni][3]);
        }
    }
}

// ============================================================
// CSR construction  (edge_index int32: row 0 = src, row 1 = dst)
// ============================================================
__global__ void zero_cnt_k(int M)
{
    int i = blockIdx.x * blockDim.x + threadIdx.x;
    if (i < M) g_cnt[i] = 0;
}

__global__ void count_k(const int* __restrict__ ei, int E)
{
    int e = blockIdx.x * blockDim.x + threadIdx.x;
    if (e < E) atomicAdd(&g_cnt[ei[E + e]], 1);
}

__global__ void scan1_k(int M)
{
    __shared__ int s[1024];
    int gi = blockIdx.x * 1024 + threadIdx.x;
    int v = (gi < M) ? g_cnt[gi] : 0;
    s[threadIdx.x] = v;
    __syncthreads();
#pragma unroll
    for (int off = 1; off < 1024; off <<= 1) {
        int tv = (threadIdx.x >= off) ? s[threadIdx.x - off] : 0;
        __syncthreads();
        s[threadIdx.x] += tv;
        __syncthreads();
    }
    if (gi < M) g_incl[gi] = s[threadIdx.x];
    if (threadIdx.x == 1023) g_bsum[blockIdx.x] = s[1023];
}

__global__ void scan2_k(int nb)
{
    if (threadIdx.x == 0 && blockIdx.x == 0) {
        int run = 0;
        for (int b = 0; b < nb; b++) { int tv = g_bsum[b]; g_bsum[b] = run; run += tv; }
    }
}

__global__ void scan3_k(int M)
{
    int i = blockIdx.x * blockDim.x + threadIdx.x;
    if (i < M) {
        int incl = g_incl[i] + g_bsum[i >> 10];
        g_incl[i] = incl;
        g_cursor[i] = incl - g_cnt[i];
    }
}

__global__ void scatter_k(const int* __restrict__ ei, int E)
{
    int e = blockIdx.x * blockDim.x + threadIdx.x;
    if (e < E) {
        int d = ei[E + e];
        int pos = atomicAdd(&g_cursor[d], 1);
        g_srcs[pos] = ei[e];
    }
}

// ============================================================
// GATv2 attention + aggregation, one warp per dst node.
// Lane l owns channels 8l..8l+7, all in head l>>3 (64-ch heads).
// Per-edge: one 8-lane (3-SHFL) segmented reduction.
// ============================================================
__device__ __forceinline__ float leaky4dot(float4 xl, float4 xr, float4 at)
{
    float z0 = xl.x + xr.x, z1 = xl.y + xr.y, z2 = xl.z + xr.z, z3 = xl.w + xr.w;
    float l0 = z0 > 0.f ? z0 : NEG_SLOPE * z0;
    float l1 = z1 > 0.f ? z1 : NEG_SLOPE * z1;
    float l2 = z2 > 0.f ? z2 : NEG_SLOPE * z2;
    float l3 = z3 > 0.f ? z3 : NEG_SLOPE * z3;
    return at.x * l0 + at.y * l1 + at.z * l2 + at.w * l3;
}

__device__ __forceinline__ float red8(float v)
{
    v += __shfl_xor_sync(0xffffffffu, v, 1);
    v += __shfl_xor_sync(0xffffffffu, v, 2);
    v += __shfl_xor_sync(0xffffffffu, v, 4);
    return v;
}

__global__ void __launch_bounds__(256)
agg_k(const float* __restrict__ att, const float* __restrict__ bias,
      float* __restrict__ out, int M)
{
    const int gwarp = (blockIdx.x * blockDim.x + threadIdx.x) >> 5;
    const int lane = threadIdx.x & 31;
    if (gwarp >= M) return;
    const int i = gwarp;
    const int c0 = lane * 8;

    float4 atA = *(const float4*)&att[c0];
    float4 atB = *(const float4*)&att[c0 + 4];
    const float* xrp = g_xr + (size_t)i * D_IN;
    float4 xrA = *(const float4*)&xrp[c0];
    float4 xrB = *(const float4*)&xrp[c0 + 4];

    float m, d;
    float4 accA, accB;

    // ---- self loop (weight exp(0)=1) ----
    {
        const float* xlp = g_xl + (size_t)i * D_IN;
        float4 xlA = *(const float4*)&xlp[c0];
        float4 xlB = *(const float4*)&xlp[c0 + 4];
        m = red8(leaky4dot(xlA, xrA, atA) + leaky4dot(xlB, xrB, atB));
        d = 1.f;
        accA = xlA; accB = xlB;
    }

    const int end = g_incl[i];
    int j = end - g_cnt[i];

    if (j < end) {
        int src = g_srcs[j];
        const float* xlp = g_xl + (size_t)src * D_IN;
        float4 nA = *(const float4*)&xlp[c0];
        float4 nB = *(const float4*)&xlp[c0 + 4];
        for (; j < end; j++) {
            float4 xlA = nA, xlB = nB;
            if (j + 1 < end) {
                int s2 = g_srcs[j + 1];
                const float* xp = g_xl + (size_t)s2 * D_IN;
                nA = *(const float4*)&xp[c0];
                nB = *(const float4*)&xp[c0 + 4];
            }
            float p = red8(leaky4dot(xlA, xrA, atA) + leaky4dot(xlB, xrB, atB));

            float mn = fmaxf(m, p);
            float cw = __expf(m - mn), ww = __expf(p - mn);
            d = d * cw + ww; m = mn;
            accA.x = accA.x * cw + ww * xlA.x;
            accA.y = accA.y * cw + ww * xlA.y;
            accA.z = accA.z * cw + ww * xlA.z;
            accA.w = accA.w * cw + ww * xlA.w;
            accB.x = accB.x * cw + ww * xlB.x;
            accB.y = accB.y * cw + ww * xlB.y;
            accB.z = accB.z * cw + ww * xlB.z;
            accB.w = accB.w * cw + ww * xlB.w;
        }
    }

    float inv = 1.f / (d + 1e-16f);
    float z[8] = { accA.x * inv, accA.y * inv, accA.z * inv, accA.w * inv,
                   accB.x * inv, accB.y * inv, accB.z * inv, accB.w * inv };
    // mean over heads: lanes l, l^8, l^16, l^24 hold the same per-head channel
#pragma unroll
    for (int q = 0; q < 8; q++) {
        z[q] += __shfl_xor_sync(0xffffffffu, z[q], 8);
        z[q] += __shfl_xor_sync(0xffffffffu, z[q], 16);
    }

    if (lane < 8) {
#pragma unroll
        for (int q = 0; q < 8; q++) {
            float o = 0.25f * z[q] + bias[c0 + q];
            z[q] = o > 0.f ? o : expm1f(o);
        }
        float* dst = out + (size_t)i * D_OUT + c0;
        *(float4*)dst = make_float4(z[0], z[1], z[2], z[3]);
        *(float4*)(dst + 4) = make_float4(z[4], z[5], z[6], z[7]);
    }
}

// ============================================================
extern "C" void kernel_launch(void* const* d_in, const int* in_sizes, int n_in,
                              void* d_out, int out_size)
{
    const int* ei        = (const int*)d_in[1];
    const float* emb     = (const float*)d_in[2];
    const float* Wl      = (const float*)d_in[3];
    const float* Wr      = (const float*)d_in[4];
    const float* att     = (const float*)d_in[5];
    const float* bias    = (const float*)d_in[6];
    float* out           = (float*)d_out;

    const int E = in_sizes[1] / 2;         // 1,600,000
    const int M = in_sizes[2] / D_IN;      // 100,000
    const int T = (M + 127) / 128;         // 782 row tiles
    const int MP = T * 128;

    const int GEMM_SMEM = 2 * STAGE_B;     // 81920 B
    static int smem_set = 0;
    if (!smem_set) {
        cudaFuncSetAttribute(gemm_mma, cudaFuncAttributeMaxDynamicSharedMemorySize,
                             GEMM_SMEM);
        smem_set = 1;
    }

    // 1) bf16 hi/lo prep + mma.sync GEMM (xl and xr in one pass)
    int n4 = M * 64, np4 = MP * 64;
    prepA_k<<<(np4 + 255) / 256, 256>>>((const float4*)emb, n4, np4);
    prepW_k<<<512, 256>>>(Wl, Wr);
    gemm_mma<<<dim3(4, T), 256, GEMM_SMEM>>>();

    // 2) CSR by dst
    int tb = 256;
    zero_cnt_k<<<(M + tb - 1) / tb, tb>>>(M);
    count_k<<<(E + tb - 1) / tb, tb>>>(ei, E);
    int nb = (M + 1023) / 1024;
    scan1_k<<<nb, 1024>>>(M);
    scan2_k<<<1, 32>>>(nb);
    scan3_k<<<(M + tb - 1) / tb, tb>>>(M);
    scatter_k<<<(E + tb - 1) / tb, tb>>>(ei, E);

    // 3) attention + aggregation (one warp per node)
    int nblk = (M + 7) / 8;
    agg_k<<<nblk, 256>>>(att, bias, out, M);

    (void)n_in; (void)out_size;
}